// round 9
// baseline (speedup 1.0000x reference)
#include <cuda_runtime.h>
#include <math.h>

#define B_   4
#define S_   8192
#define D_   128
#define H_   8
#define SP_  1024
#define BH_  (B_*H_)
#define NROWS (B_*S_)      // 32768
#define MAXC 64
#define OUT_ELEMS  (B_*S_*D_)
#define ATTN_ELEMS (BH_*SP_*SP_)

#define GEMM_BLOCKS (NROWS / 128)   // 256
#define ROWS_PER_BLOCK (NROWS / GEMM_BLOCKS)  // 128 attn rows per gemm block

// Scratch (device globals)
__device__ float g_Ublend[NROWS*D_];   // blended v rows (rare multi-cand rows)
__device__ float g_rareP[NROWS*MAXC];  // softmax probs for rare rows
__device__ float g_W2[D_*D_];          // Wv @ Wo
__device__ float g_b2[D_];             // bv @ Wo + bo
__device__ int   g_candK[SP_*MAXC];
__device__ int   g_candCnt[SP_];

// row s in (B, S) order -> row in (B, H, Sp) order
__device__ __forceinline__ int split_row(int s) {
    int b = s >> 13;
    int r = s & 8191;
    return (((b << 3) | (r & 7)) << 10) | (r >> 3);
}

// ---------------------------------------------------------------------------
// fused_mask_prep:
//   blocks [0,1024): mask row analysis -> g_candK / g_candCnt
//   blocks [1024,1088): W2 = Wv @ Wo
//   block  1088: b2 = bv @ Wo + bo
// (mask analysis and W2/b2 are independent -> one launch)
// ---------------------------------------------------------------------------
__global__ __launch_bounds__(256) void fused_mask_prep(
    const float* __restrict__ mask,
    const float* __restrict__ Wv, const float* __restrict__ Wo,
    const float* __restrict__ bv, const float* __restrict__ bo)
{
    if (blockIdx.x < SP_) {
        const int q = blockIdx.x;
        const int t = threadIdx.x;
        __shared__ float wmax[8];
        __shared__ int cnt;

        const float4 mv = *(const float4*)(mask + (size_t)q * SP_ + t*4);
        float v[4] = { mv.x * (-1e9f), mv.y * (-1e9f),
                       mv.z * (-1e9f), mv.w * (-1e9f) };
        float m = fmaxf(fmaxf(v[0], v[1]), fmaxf(v[2], v[3]));
#pragma unroll
        for (int o = 16; o > 0; o >>= 1)
            m = fmaxf(m, __shfl_xor_sync(0xffffffffu, m, o));
        if ((t & 31) == 0) wmax[t >> 5] = m;
        if (t == 0) cnt = 0;
        __syncthreads();
        float rowmax = wmax[0];
#pragma unroll
        for (int i = 1; i < 8; i++) rowmax = fmaxf(rowmax, wmax[i]);
#pragma unroll
        for (int j = 0; j < 4; j++) {
            if (v[j] >= rowmax - 300.0f) {
                int slot = atomicAdd(&cnt, 1);
                if (slot < MAXC) g_candK[q*MAXC + slot] = t*4 + j;
            }
        }
        __syncthreads();
        if (t == 0) g_candCnt[q] = (cnt < MAXC) ? cnt : MAXC;
        return;
    }
    if (blockIdx.x < SP_ + 64) {
        const int idx = (blockIdx.x - SP_) * 256 + threadIdx.x;
        const int r = idx >> 7;
        const int c = idx & 127;
        const float* wr = Wv + (size_t)r * D_;
        const float* wc = Wo + c;
        float a0 = 0.f, a1 = 0.f, a2 = 0.f, a3 = 0.f;
#pragma unroll
        for (int k = 0; k < D_; k += 4) {
            a0 = fmaf(wr[k+0], wc[(size_t)(k+0) * D_], a0);
            a1 = fmaf(wr[k+1], wc[(size_t)(k+1) * D_], a1);
            a2 = fmaf(wr[k+2], wc[(size_t)(k+2) * D_], a2);
            a3 = fmaf(wr[k+3], wc[(size_t)(k+3) * D_], a3);
        }
        g_W2[idx] = (a0 + a1) + (a2 + a3);
        return;
    }
    // b2
    const int c = threadIdx.x;
    if (c >= D_) return;
    const float* wc = Wo + c;
    float a[8] = {0.f,0.f,0.f,0.f,0.f,0.f,0.f,0.f};
#pragma unroll
    for (int k = 0; k < D_; k += 8) {
#pragma unroll
        for (int u = 0; u < 8; u++)
            a[u] = fmaf(bv[k+u], wc[(size_t)(k+u) * D_], a[u]);
    }
    g_b2[c] = ((a[0]+a[1]) + (a[2]+a[3])) + ((a[4]+a[5]) + (a[6]+a[7])) + bo[c];
}

// ---------------------------------------------------------------------------
// Rare-row handler: block per mask row q; early exit unless cnt>=2.
// 8 warps x 4 bh each: exact fp32 Q/K matvecs, softmax, blend into g_Ublend,
// probs into g_rareP.
// ---------------------------------------------------------------------------
__global__ __launch_bounds__(256) void rare_attn(
    const float* __restrict__ qin, const float* __restrict__ kin,
    const float* __restrict__ vin, const float* __restrict__ mask,
    const float* __restrict__ Wq, const float* __restrict__ bq,
    const float* __restrict__ Wk, const float* __restrict__ bk)
{
    const int q = blockIdx.x;
    const int cnt = g_candCnt[q];
    if (cnt < 2) return;

    __shared__ float sx[8][MAXC];
    const int w    = threadIdx.x >> 5;
    const int lane = threadIdx.x & 31;

    for (int bh = w * 4; bh < w * 4 + 4; bh++) {
        const int b = bh >> 3;
        const int h = bh & 7;
        const int bhrow = bh * SP_ + q;

        const float* qrow = qin + (size_t)(b * S_ + q * H_ + h) * D_;
        float4 qv = *(const float4*)(qrow + lane*4);
        float qp[4] = { bq[lane*4+0], bq[lane*4+1], bq[lane*4+2], bq[lane*4+3] };
        for (int kk0 = 0; kk0 < D_; kk0 += 4) {
            const int src = kk0 >> 2;
            float c0 = __shfl_sync(0xffffffffu, qv.x, src);
            float c1 = __shfl_sync(0xffffffffu, qv.y, src);
            float c2 = __shfl_sync(0xffffffffu, qv.z, src);
            float c3 = __shfl_sync(0xffffffffu, qv.w, src);
            const float* wp = Wq + (size_t)kk0 * D_ + lane*4;
            float4 w0 = *(const float4*)(wp);
            float4 w1 = *(const float4*)(wp + D_);
            float4 w2 = *(const float4*)(wp + 2*D_);
            float4 w3 = *(const float4*)(wp + 3*D_);
            qp[0] = fmaf(c0,w0.x,fmaf(c1,w1.x,fmaf(c2,w2.x,fmaf(c3,w3.x,qp[0]))));
            qp[1] = fmaf(c0,w0.y,fmaf(c1,w1.y,fmaf(c2,w2.y,fmaf(c3,w3.y,qp[1]))));
            qp[2] = fmaf(c0,w0.z,fmaf(c1,w1.z,fmaf(c2,w2.z,fmaf(c3,w3.z,qp[2]))));
            qp[3] = fmaf(c0,w0.w,fmaf(c1,w1.w,fmaf(c2,w2.w,fmaf(c3,w3.w,qp[3]))));
        }

        float m = -3.4e38f;
        for (int j = 0; j < cnt; j++) {
            const int k = g_candK[q*MAXC + j];
            const float* krow = kin + (size_t)(b * S_ + k * H_ + h) * D_;
            float4 kv = *(const float4*)(krow + lane*4);
            float kp[4] = { bk[lane*4+0], bk[lane*4+1], bk[lane*4+2], bk[lane*4+3] };
            for (int kk0 = 0; kk0 < D_; kk0 += 4) {
                const int src = kk0 >> 2;
                float c0 = __shfl_sync(0xffffffffu, kv.x, src);
                float c1 = __shfl_sync(0xffffffffu, kv.y, src);
                float c2 = __shfl_sync(0xffffffffu, kv.z, src);
                float c3 = __shfl_sync(0xffffffffu, kv.w, src);
                const float* wp = Wk + (size_t)kk0 * D_ + lane*4;
                float4 w0 = *(const float4*)(wp);
                float4 w1 = *(const float4*)(wp + D_);
                float4 w2 = *(const float4*)(wp + 2*D_);
                float4 w3 = *(const float4*)(wp + 3*D_);
                kp[0] = fmaf(c0,w0.x,fmaf(c1,w1.x,fmaf(c2,w2.x,fmaf(c3,w3.x,kp[0]))));
                kp[1] = fmaf(c0,w0.y,fmaf(c1,w1.y,fmaf(c2,w2.y,fmaf(c3,w3.y,kp[1]))));
                kp[2] = fmaf(c0,w0.z,fmaf(c1,w1.z,fmaf(c2,w2.z,fmaf(c3,w3.z,kp[2]))));
                kp[3] = fmaf(c0,w0.w,fmaf(c1,w1.w,fmaf(c2,w2.w,fmaf(c3,w3.w,kp[3]))));
            }
            float d = qp[0]*kp[0] + qp[1]*kp[1] + qp[2]*kp[2] + qp[3]*kp[3];
#pragma unroll
            for (int o = 16; o > 0; o >>= 1)
                d += __shfl_xor_sync(0xffffffffu, d, o);
            float xv = d / 11.313708498984761f + mask[(size_t)q*SP_ + k] * (-1e9f);
            if (lane == 0) sx[w][j] = xv;
            m = fmaxf(m, xv);
        }
        __syncwarp();

        float sum = 0.f;
        for (int j = 0; j < cnt; j++) sum += expf(sx[w][j] - m);
        const float inv = 1.0f / sum;

        float4 u = make_float4(0.f, 0.f, 0.f, 0.f);
        for (int j = 0; j < cnt; j++) {
            const int k = g_candK[q*MAXC + j];
            const float p = expf(sx[w][j] - m) * inv;
            const float* vrow = vin + (size_t)(b * S_ + k * H_ + h) * D_;
            float4 vr = *(const float4*)(vrow + lane*4);
            u.x = fmaf(p, vr.x, u.x);
            u.y = fmaf(p, vr.y, u.y);
            u.z = fmaf(p, vr.z, u.z);
            u.w = fmaf(p, vr.w, u.w);
            if (lane == 0) g_rareP[(size_t)bhrow * MAXC + j] = p;
        }
        *(float4*)(g_Ublend + (size_t)bhrow * D_ + lane*4) = u;
        __syncwarp();
    }
}

// ---------------------------------------------------------------------------
// One attention-output row written by one warp (1024 floats = 8 float4/lane).
// ---------------------------------------------------------------------------
__device__ __forceinline__ void write_attn_row(
    float* __restrict__ attnOut, int gw, int lane)
{
    const int qq  = gw & 1023;
    const int cnt = g_candCnt[qq];
    float4* row = (float4*)(attnOut + (size_t)gw * SP_);

    if (cnt == 1) {
        const int k  = g_candK[qq * MAXC];
        const int kf = k >> 2;
        const int kc = k & 3;
#pragma unroll
        for (int j = 0; j < 8; j++) {
            const int f = j * 32 + lane;
            float4 val = make_float4(0.f, 0.f, 0.f, 0.f);
            if (f == kf) ((float*)&val)[kc] = 1.0f;
            row[f] = val;
        }
    } else {
        const float4 z = make_float4(0.f, 0.f, 0.f, 0.f);
#pragma unroll
        for (int j = 0; j < 8; j++)
            row[j * 32 + lane] = z;
        __syncwarp();
        if (lane == 0) {
            for (int j = 0; j < cnt; j++)
                attnOut[(size_t)gw * SP_ + g_candK[qq*MAXC + j]] =
                    g_rareP[(size_t)gw * MAXC + j];
        }
        __syncwarp();
    }
}

// ---------------------------------------------------------------------------
// fused_main: 256 blocks. Each block computes one 128x128 GEMM tile of
// out = gather(v) @ W2 + b2 AND writes 128 attention-output rows, with the
// row writes interleaved into the k0 loop (16 rows per iteration, 2 per
// warp). FFMA (fma pipe) and STG (LSU/DRAM) issue concurrently from the
// same resident blocks -> overlap by construction, no co-scheduling needed.
// ---------------------------------------------------------------------------
__global__ __launch_bounds__(256) void fused_main(
    const float* __restrict__ A, float* __restrict__ C,
    float* __restrict__ attnOut, int hasAttn)
{
    __shared__ float AsT[16][132];
    __shared__ float Bs[16][128];

    const int t    = threadIdx.x;
    const int row0 = blockIdx.x * 128;
    const int ty   = t >> 4;
    const int tx   = t & 15;
    const int w    = t >> 5;
    const int lane = t & 31;
    const int attnBase = blockIdx.x * ROWS_PER_BLOCK;

    float acc[8][8];
#pragma unroll
    for (int i = 0; i < 8; i++)
#pragma unroll
        for (int j = 0; j < 8; j++) acc[i][j] = 0.f;

    const int lrow = t >> 1;
    const int lc0  = (t & 1) * 8;
    const int s_in = row0 + lrow;
    const int bhrow = split_row(s_in);
    const int qq  = bhrow & 1023;
    const int cnt = g_candCnt[qq];
    const float* arow;
    if (cnt == 1) {
        const int bh = bhrow >> 10;
        const int k  = g_candK[qq * MAXC];
        arow = A + (size_t)((bh >> 3) * S_ + k * H_ + (bh & 7)) * D_;
    } else {
        arow = g_Ublend + (size_t)bhrow * D_;
    }

    const int br = t >> 4, bc = (t & 15) * 8;

    for (int it = 0; it < 8; it++) {
        const int k0 = it * 16;
        float4 a0 = *(const float4*)(arow + k0 + lc0);
        float4 a1 = *(const float4*)(arow + k0 + lc0 + 4);
        AsT[lc0+0][lrow] = a0.x; AsT[lc0+1][lrow] = a0.y;
        AsT[lc0+2][lrow] = a0.z; AsT[lc0+3][lrow] = a0.w;
        AsT[lc0+4][lrow] = a1.x; AsT[lc0+5][lrow] = a1.y;
        AsT[lc0+6][lrow] = a1.z; AsT[lc0+7][lrow] = a1.w;

        float4 b0 = *(const float4*)(g_W2 + (size_t)(k0 + br) * D_ + bc);
        float4 b1 = *(const float4*)(g_W2 + (size_t)(k0 + br) * D_ + bc + 4);
        *(float4*)&Bs[br][bc]     = b0;
        *(float4*)&Bs[br][bc + 4] = b1;
        __syncthreads();

        // Interleaved attention-output writes: 2 rows per warp per iter.
        if (hasAttn) {
            write_attn_row(attnOut, attnBase + it*16 + w*2 + 0, lane);
            write_attn_row(attnOut, attnBase + it*16 + w*2 + 1, lane);
        }

#pragma unroll
        for (int kk = 0; kk < 16; kk++) {
            float a[8], b[8];
            *(float4*)&a[0] = *(const float4*)&AsT[kk][ty*8];
            *(float4*)&a[4] = *(const float4*)&AsT[kk][ty*8 + 4];
            *(float4*)&b[0] = *(const float4*)&Bs[kk][tx*4];
            *(float4*)&b[4] = *(const float4*)&Bs[kk][64 + tx*4];
#pragma unroll
            for (int i = 0; i < 8; i++)
#pragma unroll
                for (int j = 0; j < 8; j++)
                    acc[i][j] = fmaf(a[i], b[j], acc[i][j]);
        }
        __syncthreads();
    }

    const float4 bias0 = *(const float4*)(g_b2 + tx*4);
    const float4 bias1 = *(const float4*)(g_b2 + 64 + tx*4);
#pragma unroll
    for (int i = 0; i < 8; i++) {
        int rout = row0 + ty*8 + i;
        float4 o0 = make_float4(acc[i][0] + bias0.x, acc[i][1] + bias0.y,
                                acc[i][2] + bias0.z, acc[i][3] + bias0.w);
        float4 o1 = make_float4(acc[i][4] + bias1.x, acc[i][5] + bias1.y,
                                acc[i][6] + bias1.z, acc[i][7] + bias1.w);
        *(float4*)(C + (size_t)rout * D_ + tx*4)      = o0;
        *(float4*)(C + (size_t)rout * D_ + 64 + tx*4) = o1;
    }
}

// ---------------------------------------------------------------------------
extern "C" void kernel_launch(void* const* d_in, const int* in_sizes, int n_in,
                              void* d_out, int out_size)
{
    const float* v    = (const float*)d_in[0];
    const float* k    = (const float*)d_in[1];
    const float* q    = (const float*)d_in[2];
    const float* mask = (const float*)d_in[3];
    const float* Wq   = (const float*)d_in[4];
    const float* bq   = (const float*)d_in[5];
    const float* Wk   = (const float*)d_in[6];
    const float* bk   = (const float*)d_in[7];
    const float* Wv   = (const float*)d_in[8];
    const float* bv   = (const float*)d_in[9];
    const float* Wo   = (const float*)d_in[10];
    const float* bo   = (const float*)d_in[11];
    float* out = (float*)d_out;

    const int hasAttn = (out_size >= OUT_ELEMS + ATTN_ELEMS) ? 1 : 0;
    float* attnOut = hasAttn ? (out + OUT_ELEMS) : nullptr;

    // 1. Mask candidate analysis + W2/b2 prep (independent, one launch)
    fused_mask_prep<<<SP_ + 65, 256>>>(mask, Wv, Wo, bv, bo);

    // 2. Rare-row attention (early exit on the overwhelmingly common case)
    rare_attn<<<SP_, 256>>>(q, k, v, mask, Wq, bq, Wk, bk);

    // 3. GEMM with interleaved attention-output writes (one wave, 256 blocks)
    fused_main<<<GEMM_BLOCKS, 256>>>(v, out, attnOut, hasAttn);
}

// round 10
// speedup vs baseline: 1.1385x; 1.1385x over previous
#include <cuda_runtime.h>
#include <math.h>

#define B_   4
#define S_   8192
#define D_   128
#define H_   8
#define SP_  1024
#define BH_  (B_*H_)
#define NROWS (B_*S_)      // 32768
#define MAXC 64
#define OUT_ELEMS  (B_*S_*D_)
#define ATTN_ELEMS (BH_*SP_*SP_)

#define GEMM_BLOCKS (NROWS / 128)   // 256

// Scratch (device globals)
__device__ float g_Ublend[NROWS*D_];   // blended v rows (rare multi-cand rows)
__device__ float g_rareP[NROWS*MAXC];  // softmax probs for rare rows
__device__ float g_W2[D_*D_];          // Wv @ Wo
__device__ float g_b2[D_];             // bv @ Wo + bo
__device__ int   g_candK[SP_*MAXC];
__device__ int   g_candCnt[SP_];

// row s in (B, S) order -> row in (B, H, Sp) order
__device__ __forceinline__ int split_row(int s) {
    int b = s >> 13;
    int r = s & 8191;
    return (((b << 3) | (r & 7)) << 10) | (r >> 3);
}

// ---- Blackwell packed dual-fp32 FMA helpers (lane-wise IEEE fp32, exact) ----
__device__ __forceinline__ unsigned long long pack2(float lo, float hi) {
    unsigned long long r;
    asm("mov.b64 %0, {%1, %2};" : "=l"(r) : "f"(lo), "f"(hi));
    return r;
}
__device__ __forceinline__ void unpack2(unsigned long long v, float& lo, float& hi) {
    asm("mov.b64 {%0, %1}, %2;" : "=f"(lo), "=f"(hi) : "l"(v));
}
__device__ __forceinline__ unsigned long long fma2(
    unsigned long long a, unsigned long long b, unsigned long long c) {
    unsigned long long d;
    asm("fma.rn.f32x2 %0, %1, %2, %3;" : "=l"(d) : "l"(a), "l"(b), "l"(c));
    return d;
}

// ---------------------------------------------------------------------------
// Mask row analysis, warp-per-row: candidates within 300 of row max of
// mask*(-1e9). Ballot-free enumeration via per-lane bitmask + warp scan.
// 128 blocks x 8 warps = 1024 rows.
// ---------------------------------------------------------------------------
__global__ __launch_bounds__(256) void mask_cand(const float* __restrict__ mask)
{
    const int warp = threadIdx.x >> 5;
    const int lane = threadIdx.x & 31;
    const int q    = blockIdx.x * 8 + warp;

    const float4* row4 = (const float4*)(mask + (size_t)q * SP_);
    float v[32];
    float m = -3.4e38f;
#pragma unroll
    for (int j = 0; j < 8; j++) {
        float4 t = row4[j*32 + lane];
        v[j*4+0] = t.x * (-1e9f);
        v[j*4+1] = t.y * (-1e9f);
        v[j*4+2] = t.z * (-1e9f);
        v[j*4+3] = t.w * (-1e9f);
        m = fmaxf(m, fmaxf(fmaxf(v[j*4+0], v[j*4+1]),
                           fmaxf(v[j*4+2], v[j*4+3])));
    }
#pragma unroll
    for (int o = 16; o > 0; o >>= 1)
        m = fmaxf(m, __shfl_xor_sync(0xffffffffu, m, o));
    const float thr = m - 300.0f;

    unsigned int flags = 0;
#pragma unroll
    for (int b = 0; b < 32; b++)
        if (v[b] >= thr) flags |= 1u << b;

    const int cnt = __popc(flags);
    int x = cnt;
#pragma unroll
    for (int o = 1; o < 32; o <<= 1) {
        int y = __shfl_up_sync(0xffffffffu, x, o);
        if (lane >= o) x += y;
    }
    const int excl = x - cnt;
    const int tot  = __shfl_sync(0xffffffffu, x, 31);

    int pos = excl;
    unsigned int f = flags;
    while (f) {
        int b = __ffs(f) - 1;
        f &= f - 1;
        if (pos < MAXC) {
            int j = b >> 2, c = b & 3;
            g_candK[q*MAXC + pos] = (j*32 + lane)*4 + c;
        }
        pos++;
    }
    if (lane == 0) g_candCnt[q] = (tot < MAXC) ? tot : MAXC;
}

// ---------------------------------------------------------------------------
// fused_prep: blocks 0..63 -> W2 = Wv@Wo (ILP=16 for latency); block 64 ->
// b2 = bv@Wo + bo; blocks 65..1088 -> rare-row attention (early exit).
// ---------------------------------------------------------------------------
__global__ __launch_bounds__(256) void fused_prep(
    const float* __restrict__ Wv, const float* __restrict__ Wo,
    const float* __restrict__ bv, const float* __restrict__ bo,
    const float* __restrict__ qin, const float* __restrict__ kin,
    const float* __restrict__ vin, const float* __restrict__ mask,
    const float* __restrict__ Wq, const float* __restrict__ bq,
    const float* __restrict__ Wk, const float* __restrict__ bk)
{
    if (blockIdx.x < 64) {
        const int idx = blockIdx.x * 256 + threadIdx.x;
        const int r = idx >> 7;
        const int c = idx & 127;
        const float* wr = Wv + (size_t)r * D_;
        const float* wc = Wo + c;
        float a[16];
#pragma unroll
        for (int u = 0; u < 16; u++) a[u] = 0.f;
        for (int k0 = 0; k0 < D_; k0 += 16) {
#pragma unroll
            for (int u = 0; u < 16; u++)
                a[u] = fmaf(wr[k0+u], wc[(size_t)(k0+u) * D_], a[u]);
        }
        float s = 0.f;
#pragma unroll
        for (int u = 0; u < 16; u++) s += a[u];
        g_W2[idx] = s;
        return;
    }
    if (blockIdx.x == 64) {
        const int c = threadIdx.x;
        if (c >= D_) return;
        const float* wc = Wo + c;
        float a[16];
#pragma unroll
        for (int u = 0; u < 16; u++) a[u] = 0.f;
        for (int k0 = 0; k0 < D_; k0 += 16) {
#pragma unroll
            for (int u = 0; u < 16; u++)
                a[u] = fmaf(bv[k0+u], wc[(size_t)(k0+u) * D_], a[u]);
        }
        float s = 0.f;
#pragma unroll
        for (int u = 0; u < 16; u++) s += a[u];
        g_b2[c] = s + bo[c];
        return;
    }

    // ---- rare rows ----
    const int q = blockIdx.x - 65;
    const int cnt = g_candCnt[q];
    if (cnt < 2) return;

    __shared__ float sx[8][MAXC];
    const int w    = threadIdx.x >> 5;
    const int lane = threadIdx.x & 31;

    for (int bh = w * 4; bh < w * 4 + 4; bh++) {
        const int b = bh >> 3;
        const int h = bh & 7;
        const int bhrow = bh * SP_ + q;

        const float* qrow = qin + (size_t)(b * S_ + q * H_ + h) * D_;
        float4 qv = *(const float4*)(qrow + lane*4);
        float qp[4] = { bq[lane*4+0], bq[lane*4+1], bq[lane*4+2], bq[lane*4+3] };
        for (int kk0 = 0; kk0 < D_; kk0 += 4) {
            const int src = kk0 >> 2;
            float c0 = __shfl_sync(0xffffffffu, qv.x, src);
            float c1 = __shfl_sync(0xffffffffu, qv.y, src);
            float c2 = __shfl_sync(0xffffffffu, qv.z, src);
            float c3 = __shfl_sync(0xffffffffu, qv.w, src);
            const float* wp = Wq + (size_t)kk0 * D_ + lane*4;
            float4 w0 = *(const float4*)(wp);
            float4 w1 = *(const float4*)(wp + D_);
            float4 w2 = *(const float4*)(wp + 2*D_);
            float4 w3 = *(const float4*)(wp + 3*D_);
            qp[0] = fmaf(c0,w0.x,fmaf(c1,w1.x,fmaf(c2,w2.x,fmaf(c3,w3.x,qp[0]))));
            qp[1] = fmaf(c0,w0.y,fmaf(c1,w1.y,fmaf(c2,w2.y,fmaf(c3,w3.y,qp[1]))));
            qp[2] = fmaf(c0,w0.z,fmaf(c1,w1.z,fmaf(c2,w2.z,fmaf(c3,w3.z,qp[2]))));
            qp[3] = fmaf(c0,w0.w,fmaf(c1,w1.w,fmaf(c2,w2.w,fmaf(c3,w3.w,qp[3]))));
        }

        float m = -3.4e38f;
        for (int j = 0; j < cnt; j++) {
            const int k = g_candK[q*MAXC + j];
            const float* krow = kin + (size_t)(b * S_ + k * H_ + h) * D_;
            float4 kv = *(const float4*)(krow + lane*4);
            float kp[4] = { bk[lane*4+0], bk[lane*4+1], bk[lane*4+2], bk[lane*4+3] };
            for (int kk0 = 0; kk0 < D_; kk0 += 4) {
                const int src = kk0 >> 2;
                float c0 = __shfl_sync(0xffffffffu, kv.x, src);
                float c1 = __shfl_sync(0xffffffffu, kv.y, src);
                float c2 = __shfl_sync(0xffffffffu, kv.z, src);
                float c3 = __shfl_sync(0xffffffffu, kv.w, src);
                const float* wp = Wk + (size_t)kk0 * D_ + lane*4;
                float4 w0 = *(const float4*)(wp);
                float4 w1 = *(const float4*)(wp + D_);
                float4 w2 = *(const float4*)(wp + 2*D_);
                float4 w3 = *(const float4*)(wp + 3*D_);
                kp[0] = fmaf(c0,w0.x,fmaf(c1,w1.x,fmaf(c2,w2.x,fmaf(c3,w3.x,kp[0]))));
                kp[1] = fmaf(c0,w0.y,fmaf(c1,w1.y,fmaf(c2,w2.y,fmaf(c3,w3.y,kp[1]))));
                kp[2] = fmaf(c0,w0.z,fmaf(c1,w1.z,fmaf(c2,w2.z,fmaf(c3,w3.z,kp[2]))));
                kp[3] = fmaf(c0,w0.w,fmaf(c1,w1.w,fmaf(c2,w2.w,fmaf(c3,w3.w,kp[3]))));
            }
            float d = qp[0]*kp[0] + qp[1]*kp[1] + qp[2]*kp[2] + qp[3]*kp[3];
#pragma unroll
            for (int o = 16; o > 0; o >>= 1)
                d += __shfl_xor_sync(0xffffffffu, d, o);
            float xv = d / 11.313708498984761f + mask[(size_t)q*SP_ + k] * (-1e9f);
            if (lane == 0) sx[w][j] = xv;
            m = fmaxf(m, xv);
        }
        __syncwarp();

        float sum = 0.f;
        for (int j = 0; j < cnt; j++) sum += expf(sx[w][j] - m);
        const float inv = 1.0f / sum;

        float4 u = make_float4(0.f, 0.f, 0.f, 0.f);
        for (int j = 0; j < cnt; j++) {
            const int k = g_candK[q*MAXC + j];
            const float p = expf(sx[w][j] - m) * inv;
            const float* vrow = vin + (size_t)(b * S_ + k * H_ + h) * D_;
            float4 vr = *(const float4*)(vrow + lane*4);
            u.x = fmaf(p, vr.x, u.x);
            u.y = fmaf(p, vr.y, u.y);
            u.z = fmaf(p, vr.z, u.z);
            u.w = fmaf(p, vr.w, u.w);
            if (lane == 0) g_rareP[(size_t)bhrow * MAXC + j] = p;
        }
        *(float4*)(g_Ublend + (size_t)bhrow * D_ + lane*4) = u;
        __syncwarp();
    }
}

// ---------------------------------------------------------------------------
// Attention output writer: one warp per bh-row (streaming stores).
// ---------------------------------------------------------------------------
__global__ __launch_bounds__(256) void attn_write(float* __restrict__ attnOut)
{
    const int gw   = (blockIdx.x * 256 + threadIdx.x) >> 5;  // 0..32767
    const int lane = threadIdx.x & 31;
    const int qq   = gw & 1023;
    const int cnt  = g_candCnt[qq];
    float4* row = (float4*)(attnOut + (size_t)gw * SP_);

    if (cnt == 1) {
        const int k  = g_candK[qq * MAXC];
        const int kf = k >> 2;
        const int kc = k & 3;
#pragma unroll
        for (int j = 0; j < 8; j++) {
            const int f = j * 32 + lane;
            float4 val = make_float4(0.f, 0.f, 0.f, 0.f);
            if (f == kf) ((float*)&val)[kc] = 1.0f;
            __stcs(&row[f], val);
        }
    } else {
        const float4 z = make_float4(0.f, 0.f, 0.f, 0.f);
#pragma unroll
        for (int j = 0; j < 8; j++)
            __stcs(&row[j * 32 + lane], z);
        __syncwarp();
        if (lane == 0) {
            for (int j = 0; j < cnt; j++)
                attnOut[(size_t)gw * SP_ + g_candK[qq*MAXC + j]] =
                    g_rareP[(size_t)gw * MAXC + j];
        }
    }
}

// ---------------------------------------------------------------------------
// Main SGEMM with FFMA2: C[M x 128] = gather(v)[M x 128] @ W2 + b2.
// 8x8 micro-tile held as 8x4 packed f32x2 accumulators; inner product uses
// fma.rn.f32x2 (2 IEEE fp32 FMAs per instruction -> half the fma-pipe time).
// ---------------------------------------------------------------------------
__global__ __launch_bounds__(256) void gemm128(
    const float* __restrict__ A, float* __restrict__ C)
{
    __shared__ float AsT[16][132];
    __shared__ float Bs[16][128];

    const int t    = threadIdx.x;
    const int row0 = blockIdx.x * 128;
    const int ty   = t >> 4;
    const int tx   = t & 15;

    unsigned long long acc2[8][4];
#pragma unroll
    for (int i = 0; i < 8; i++)
#pragma unroll
        for (int j = 0; j < 4; j++) acc2[i][j] = 0ull;

    const int lrow = t >> 1;
    const int lc0  = (t & 1) * 8;
    const int s_in = row0 + lrow;
    const int bhrow = split_row(s_in);
    const int qq  = bhrow & 1023;
    const int cnt = g_candCnt[qq];
    const float* arow;
    if (cnt == 1) {
        const int bh = bhrow >> 10;
        const int k  = g_candK[qq * MAXC];
        arow = A + (size_t)((bh >> 3) * S_ + k * H_ + (bh & 7)) * D_;
    } else {
        arow = g_Ublend + (size_t)bhrow * D_;
    }

    const int br = t >> 4, bc = (t & 15) * 8;

    for (int k0 = 0; k0 < D_; k0 += 16) {
        float4 a0 = *(const float4*)(arow + k0 + lc0);
        float4 a1 = *(const float4*)(arow + k0 + lc0 + 4);
        AsT[lc0+0][lrow] = a0.x; AsT[lc0+1][lrow] = a0.y;
        AsT[lc0+2][lrow] = a0.z; AsT[lc0+3][lrow] = a0.w;
        AsT[lc0+4][lrow] = a1.x; AsT[lc0+5][lrow] = a1.y;
        AsT[lc0+6][lrow] = a1.z; AsT[lc0+7][lrow] = a1.w;

        float4 b0 = *(const float4*)(g_W2 + (size_t)(k0 + br) * D_ + bc);
        float4 b1 = *(const float4*)(g_W2 + (size_t)(k0 + br) * D_ + bc + 4);
        *(float4*)&Bs[br][bc]     = b0;
        *(float4*)&Bs[br][bc + 4] = b1;
        __syncthreads();

#pragma unroll
        for (int kk = 0; kk < 16; kk++) {
            float a[8], b[8];
            *(float4*)&a[0] = *(const float4*)&AsT[kk][ty*8];
            *(float4*)&a[4] = *(const float4*)&AsT[kk][ty*8 + 4];
            *(float4*)&b[0] = *(const float4*)&Bs[kk][tx*4];
            *(float4*)&b[4] = *(const float4*)&Bs[kk][64 + tx*4];

            unsigned long long bv[4];
#pragma unroll
            for (int j = 0; j < 4; j++) bv[j] = pack2(b[2*j], b[2*j+1]);
#pragma unroll
            for (int i = 0; i < 8; i++) {
                const unsigned long long av = pack2(a[i], a[i]);
#pragma unroll
                for (int j = 0; j < 4; j++)
                    acc2[i][j] = fma2(av, bv[j], acc2[i][j]);
            }
        }
        __syncthreads();
    }

    const float4 bias0 = *(const float4*)(g_b2 + tx*4);
    const float4 bias1 = *(const float4*)(g_b2 + 64 + tx*4);
#pragma unroll
    for (int i = 0; i < 8; i++) {
        float c0, c1, c2, c3, c4, c5, c6, c7;
        unpack2(acc2[i][0], c0, c1);
        unpack2(acc2[i][1], c2, c3);
        unpack2(acc2[i][2], c4, c5);
        unpack2(acc2[i][3], c6, c7);
        int rout = row0 + ty*8 + i;
        float4 o0 = make_float4(c0 + bias0.x, c1 + bias0.y,
                                c2 + bias0.z, c3 + bias0.w);
        float4 o1 = make_float4(c4 + bias1.x, c5 + bias1.y,
                                c6 + bias1.z, c7 + bias1.w);
        *(float4*)(C + (size_t)rout * D_ + tx*4)      = o0;
        *(float4*)(C + (size_t)rout * D_ + 64 + tx*4) = o1;
    }
}

// ---------------------------------------------------------------------------
extern "C" void kernel_launch(void* const* d_in, const int* in_sizes, int n_in,
                              void* d_out, int out_size)
{
    const float* v    = (const float*)d_in[0];
    const float* k    = (const float*)d_in[1];
    const float* q    = (const float*)d_in[2];
    const float* mask = (const float*)d_in[3];
    const float* Wq   = (const float*)d_in[4];
    const float* bq   = (const float*)d_in[5];
    const float* Wk   = (const float*)d_in[6];
    const float* bk   = (const float*)d_in[7];
    const float* Wv   = (const float*)d_in[8];
    const float* bv   = (const float*)d_in[9];
    const float* Wo   = (const float*)d_in[10];
    const float* bo   = (const float*)d_in[11];
    float* out = (float*)d_out;

    const int hasAttn = (out_size >= OUT_ELEMS + ATTN_ELEMS) ? 1 : 0;
    float* attnOut = hasAttn ? (out + OUT_ELEMS) : nullptr;

    // 1. Candidate sets per mask row (warp-per-row)
    mask_cand<<<SP_ / 8, 256>>>(mask);

    // 2. W2/b2 prep (ILP=16) + rare-row attention, one launch
    fused_prep<<<65 + SP_, 256>>>(Wv, Wo, bv, bo, q, k, v, mask,
                                  Wq, bq, Wk, bk);

    // 3. Attention output (store-bound)
    if (hasAttn) attn_write<<<NROWS / 8, 256>>>(attnOut);

    // 4. out = gather(v) @ W2 + b2  (FFMA2)
    gemm128<<<GEMM_BLOCKS, 256>>>(v, out);
}

// round 11
// speedup vs baseline: 1.1753x; 1.0323x over previous
#include <cuda_runtime.h>
#include <cuda_bf16.h>
#include <math.h>

#define B_   4
#define S_   8192
#define D_   128
#define H_   8
#define SP_  1024
#define BH_  (B_*H_)
#define NROWS (B_*S_)      // 32768
#define MAXC 64
#define OUT_ELEMS  (B_*S_*D_)
#define ATTN_ELEMS (BH_*SP_*SP_)

#define GEMM_BLOCKS (NROWS / 128)   // 256

// smem layout for gemm_mma (bf16, padded row stride 136 to kill bank conflicts)
#define APAD 136
#define A_TILE_ELEMS (128 * APAD)              // 17408 bf16
#define SMEM_BYTES   (4 * A_TILE_ELEMS * 2)    // Ah, Al, Bh, Bl = 139264 B

// Scratch (device globals)
__device__ float g_Ublend[NROWS*D_];   // blended v rows (rare multi-cand rows)
__device__ float g_rareP[NROWS*MAXC];  // softmax probs for rare rows
__device__ __nv_bfloat16 g_W2h[D_*D_]; // bf16 hi of (Wv@Wo), TRANSPOSED [n][k]
__device__ __nv_bfloat16 g_W2l[D_*D_]; // bf16 lo residual,   TRANSPOSED [n][k]
__device__ float g_b2[D_];             // bv @ Wo + bo
__device__ int   g_candK[SP_*MAXC];
__device__ int   g_candCnt[SP_];

// row s in (B, S) order -> row in (B, H, Sp) order
__device__ __forceinline__ int split_row(int s) {
    int b = s >> 13;
    int r = s & 8191;
    return (((b << 3) | (r & 7)) << 10) | (r >> 3);
}

__device__ __forceinline__ void mma_bf16(
    float& c0, float& c1, float& c2, float& c3,
    unsigned a0, unsigned a1, unsigned a2, unsigned a3,
    unsigned b0, unsigned b1)
{
    asm volatile(
        "mma.sync.aligned.m16n8k16.row.col.f32.bf16.bf16.f32 "
        "{%0,%1,%2,%3},{%4,%5,%6,%7},{%8,%9},{%0,%1,%2,%3};"
        : "+f"(c0), "+f"(c1), "+f"(c2), "+f"(c3)
        : "r"(a0), "r"(a1), "r"(a2), "r"(a3), "r"(b0), "r"(b1));
}

// ---------------------------------------------------------------------------
// Mask row analysis, warp-per-row (ballot-free enumeration via lane bitmask
// + warp prefix scan). 128 blocks x 8 warps = 1024 rows.
// ---------------------------------------------------------------------------
__global__ __launch_bounds__(256) void mask_cand(const float* __restrict__ mask)
{
    const int warp = threadIdx.x >> 5;
    const int lane = threadIdx.x & 31;
    const int q    = blockIdx.x * 8 + warp;

    const float4* row4 = (const float4*)(mask + (size_t)q * SP_);
    float v[32];
    float m = -3.4e38f;
#pragma unroll
    for (int j = 0; j < 8; j++) {
        float4 t = row4[j*32 + lane];
        v[j*4+0] = t.x * (-1e9f);
        v[j*4+1] = t.y * (-1e9f);
        v[j*4+2] = t.z * (-1e9f);
        v[j*4+3] = t.w * (-1e9f);
        m = fmaxf(m, fmaxf(fmaxf(v[j*4+0], v[j*4+1]),
                           fmaxf(v[j*4+2], v[j*4+3])));
    }
#pragma unroll
    for (int o = 16; o > 0; o >>= 1)
        m = fmaxf(m, __shfl_xor_sync(0xffffffffu, m, o));
    const float thr = m - 300.0f;

    unsigned int flags = 0;
#pragma unroll
    for (int b = 0; b < 32; b++)
        if (v[b] >= thr) flags |= 1u << b;

    const int cnt = __popc(flags);
    int x = cnt;
#pragma unroll
    for (int o = 1; o < 32; o <<= 1) {
        int y = __shfl_up_sync(0xffffffffu, x, o);
        if (lane >= o) x += y;
    }
    const int excl = x - cnt;
    const int tot  = __shfl_sync(0xffffffffu, x, 31);

    int pos = excl;
    unsigned int f = flags;
    while (f) {
        int b = __ffs(f) - 1;
        f &= f - 1;
        if (pos < MAXC) {
            int j = b >> 2, c = b & 3;
            g_candK[q*MAXC + pos] = (j*32 + lane)*4 + c;
        }
        pos++;
    }
    if (lane == 0) g_candCnt[q] = (tot < MAXC) ? tot : MAXC;
}

// ---------------------------------------------------------------------------
// fused_prep: blocks 0..63 -> W2 = Wv@Wo, emitted as TRANSPOSED bf16 hi/lo;
// block 64 -> b2; blocks 65..1088 -> rare-row attention (early exit).
// ---------------------------------------------------------------------------
__global__ __launch_bounds__(256) void fused_prep(
    const float* __restrict__ Wv, const float* __restrict__ Wo,
    const float* __restrict__ bv, const float* __restrict__ bo,
    const float* __restrict__ qin, const float* __restrict__ kin,
    const float* __restrict__ vin, const float* __restrict__ mask,
    const float* __restrict__ Wq, const float* __restrict__ bq,
    const float* __restrict__ Wk, const float* __restrict__ bk)
{
    if (blockIdx.x < 64) {
        const int idx = blockIdx.x * 256 + threadIdx.x;
        const int r = idx >> 7;       // k-dim of final gemm
        const int c = idx & 127;      // n-dim
        const float* wr = Wv + (size_t)r * D_;
        const float* wc = Wo + c;
        float a[16];
#pragma unroll
        for (int u = 0; u < 16; u++) a[u] = 0.f;
        for (int k0 = 0; k0 < D_; k0 += 16) {
#pragma unroll
            for (int u = 0; u < 16; u++)
                a[u] = fmaf(wr[k0+u], wc[(size_t)(k0+u) * D_], a[u]);
        }
        float s = 0.f;
#pragma unroll
        for (int u = 0; u < 16; u++) s += a[u];
        __nv_bfloat16 h = __float2bfloat16(s);
        __nv_bfloat16 l = __float2bfloat16(s - __bfloat162float(h));
        g_W2h[c * D_ + r] = h;      // transposed [n][k]
        g_W2l[c * D_ + r] = l;
        return;
    }
    if (blockIdx.x == 64) {
        const int c = threadIdx.x;
        if (c >= D_) return;
        const float* wc = Wo + c;
        float a[16];
#pragma unroll
        for (int u = 0; u < 16; u++) a[u] = 0.f;
        for (int k0 = 0; k0 < D_; k0 += 16) {
#pragma unroll
            for (int u = 0; u < 16; u++)
                a[u] = fmaf(bv[k0+u], wc[(size_t)(k0+u) * D_], a[u]);
        }
        float s = 0.f;
#pragma unroll
        for (int u = 0; u < 16; u++) s += a[u];
        g_b2[c] = s + bo[c];
        return;
    }

    // ---- rare rows ----
    const int q = blockIdx.x - 65;
    const int cnt = g_candCnt[q];
    if (cnt < 2) return;

    __shared__ float sx[8][MAXC];
    const int w    = threadIdx.x >> 5;
    const int lane = threadIdx.x & 31;

    for (int bh = w * 4; bh < w * 4 + 4; bh++) {
        const int b = bh >> 3;
        const int h = bh & 7;
        const int bhrow = bh * SP_ + q;

        const float* qrow = qin + (size_t)(b * S_ + q * H_ + h) * D_;
        float4 qv = *(const float4*)(qrow + lane*4);
        float qp[4] = { bq[lane*4+0], bq[lane*4+1], bq[lane*4+2], bq[lane*4+3] };
        for (int kk0 = 0; kk0 < D_; kk0 += 4) {
            const int src = kk0 >> 2;
            float c0 = __shfl_sync(0xffffffffu, qv.x, src);
            float c1 = __shfl_sync(0xffffffffu, qv.y, src);
            float c2 = __shfl_sync(0xffffffffu, qv.z, src);
            float c3 = __shfl_sync(0xffffffffu, qv.w, src);
            const float* wp = Wq + (size_t)kk0 * D_ + lane*4;
            float4 w0 = *(const float4*)(wp);
            float4 w1 = *(const float4*)(wp + D_);
            float4 w2 = *(const float4*)(wp + 2*D_);
            float4 w3 = *(const float4*)(wp + 3*D_);
            qp[0] = fmaf(c0,w0.x,fmaf(c1,w1.x,fmaf(c2,w2.x,fmaf(c3,w3.x,qp[0]))));
            qp[1] = fmaf(c0,w0.y,fmaf(c1,w1.y,fmaf(c2,w2.y,fmaf(c3,w3.y,qp[1]))));
            qp[2] = fmaf(c0,w0.z,fmaf(c1,w1.z,fmaf(c2,w2.z,fmaf(c3,w3.z,qp[2]))));
            qp[3] = fmaf(c0,w0.w,fmaf(c1,w1.w,fmaf(c2,w2.w,fmaf(c3,w3.w,qp[3]))));
        }

        float m = -3.4e38f;
        for (int j = 0; j < cnt; j++) {
            const int k = g_candK[q*MAXC + j];
            const float* krow = kin + (size_t)(b * S_ + k * H_ + h) * D_;
            float4 kv = *(const float4*)(krow + lane*4);
            float kp[4] = { bk[lane*4+0], bk[lane*4+1], bk[lane*4+2], bk[lane*4+3] };
            for (int kk0 = 0; kk0 < D_; kk0 += 4) {
                const int src = kk0 >> 2;
                float c0 = __shfl_sync(0xffffffffu, kv.x, src);
                float c1 = __shfl_sync(0xffffffffu, kv.y, src);
                float c2 = __shfl_sync(0xffffffffu, kv.z, src);
                float c3 = __shfl_sync(0xffffffffu, kv.w, src);
                const float* wp = Wk + (size_t)kk0 * D_ + lane*4;
                float4 w0 = *(const float4*)(wp);
                float4 w1 = *(const float4*)(wp + D_);
                float4 w2 = *(const float4*)(wp + 2*D_);
                float4 w3 = *(const float4*)(wp + 3*D_);
                kp[0] = fmaf(c0,w0.x,fmaf(c1,w1.x,fmaf(c2,w2.x,fmaf(c3,w3.x,kp[0]))));
                kp[1] = fmaf(c0,w0.y,fmaf(c1,w1.y,fmaf(c2,w2.y,fmaf(c3,w3.y,kp[1]))));
                kp[2] = fmaf(c0,w0.z,fmaf(c1,w1.z,fmaf(c2,w2.z,fmaf(c3,w3.z,kp[2]))));
                kp[3] = fmaf(c0,w0.w,fmaf(c1,w1.w,fmaf(c2,w2.w,fmaf(c3,w3.w,kp[3]))));
            }
            float d = qp[0]*kp[0] + qp[1]*kp[1] + qp[2]*kp[2] + qp[3]*kp[3];
#pragma unroll
            for (int o = 16; o > 0; o >>= 1)
                d += __shfl_xor_sync(0xffffffffu, d, o);
            float xv = d / 11.313708498984761f + mask[(size_t)q*SP_ + k] * (-1e9f);
            if (lane == 0) sx[w][j] = xv;
            m = fmaxf(m, xv);
        }
        __syncwarp();

        float sum = 0.f;
        for (int j = 0; j < cnt; j++) sum += expf(sx[w][j] - m);
        const float inv = 1.0f / sum;

        float4 u = make_float4(0.f, 0.f, 0.f, 0.f);
        for (int j = 0; j < cnt; j++) {
            const int k = g_candK[q*MAXC + j];
            const float p = expf(sx[w][j] - m) * inv;
            const float* vrow = vin + (size_t)(b * S_ + k * H_ + h) * D_;
            float4 vr = *(const float4*)(vrow + lane*4);
            u.x = fmaf(p, vr.x, u.x);
            u.y = fmaf(p, vr.y, u.y);
            u.z = fmaf(p, vr.z, u.z);
            u.w = fmaf(p, vr.w, u.w);
            if (lane == 0) g_rareP[(size_t)bhrow * MAXC + j] = p;
        }
        *(float4*)(g_Ublend + (size_t)bhrow * D_ + lane*4) = u;
        __syncwarp();
    }
}

// ---------------------------------------------------------------------------
// Attention output writer: one warp per bh-row (streaming stores).
// ---------------------------------------------------------------------------
__global__ __launch_bounds__(256) void attn_write(float* __restrict__ attnOut)
{
    const int gw   = (blockIdx.x * 256 + threadIdx.x) >> 5;  // 0..32767
    const int lane = threadIdx.x & 31;
    const int qq   = gw & 1023;
    const int cnt  = g_candCnt[qq];
    float4* row = (float4*)(attnOut + (size_t)gw * SP_);

    if (cnt == 1) {
        const int k  = g_candK[qq * MAXC];
        const int kf = k >> 2;
        const int kc = k & 3;
#pragma unroll
        for (int j = 0; j < 8; j++) {
            const int f = j * 32 + lane;
            float4 val = make_float4(0.f, 0.f, 0.f, 0.f);
            if (f == kf) ((float*)&val)[kc] = 1.0f;
            __stcs(&row[f], val);
        }
    } else {
        const float4 z = make_float4(0.f, 0.f, 0.f, 0.f);
#pragma unroll
        for (int j = 0; j < 8; j++)
            __stcs(&row[j * 32 + lane], z);
        __syncwarp();
        if (lane == 0) {
            for (int j = 0; j < cnt; j++)
                attnOut[(size_t)gw * SP_ + g_candK[qq*MAXC + j]] =
                    g_rareP[(size_t)gw * MAXC + j];
        }
    }
}

// ---------------------------------------------------------------------------
// Tensor-core GEMM (bf16x3 split, fp32 accum):
//   out = gather(v) @ W2 + b2, 128x128 tile per block, 8 warps.
// A tile converted in-kernel to bf16 hi/lo in smem; B (W2) preconverted
// transposed hi/lo in global, staged to smem. Per warp: m16 strip x 16
// n8-tiles; 8 k16-steps x 3 mma (AhBh + AhBl + AlBh).
// ---------------------------------------------------------------------------
__global__ __launch_bounds__(256) void gemm_mma(
    const float* __restrict__ A, float* __restrict__ C)
{
    extern __shared__ __align__(16) unsigned char smem_raw[];
    __nv_bfloat16* Ah = (__nv_bfloat16*)smem_raw;
    __nv_bfloat16* Al = Ah + A_TILE_ELEMS;
    __nv_bfloat16* Bh = Al + A_TILE_ELEMS;
    __nv_bfloat16* Bl = Bh + A_TILE_ELEMS;

    const int t    = threadIdx.x;
    const int row0 = blockIdx.x * 128;
    const int warp = t >> 5;
    const int lane = t & 31;

    // ---- stage B (bf16 hi/lo, transposed [n][k]) into padded smem ----
    {
        const int n    = t >> 1;
        const int half = (t & 1) * 64;
        const uint4* srcH = (const uint4*)(g_W2h + n * D_ + half);
        const uint4* srcL = (const uint4*)(g_W2l + n * D_ + half);
        uint4* dstH = (uint4*)(Bh + n * APAD + half);
        uint4* dstL = (uint4*)(Bl + n * APAD + half);
#pragma unroll
        for (int i = 0; i < 8; i++) { dstH[i] = srcH[i]; dstL[i] = srcL[i]; }
    }

    // ---- gather + convert A tile to bf16 hi/lo ----
    {
        const int lrow  = t >> 1;
        const int khalf = (t & 1) * 64;
        const int s_in  = row0 + lrow;
        const int bhrow = split_row(s_in);
        const int qq    = bhrow & 1023;
        const int cnt   = g_candCnt[qq];
        const float* arow;
        if (cnt == 1) {
            const int bh = bhrow >> 10;
            const int k  = g_candK[qq * MAXC];
            arow = A + (size_t)((bh >> 3) * S_ + k * H_ + (bh & 7)) * D_;
        } else {
            arow = g_Ublend + (size_t)bhrow * D_;
        }
        const float4* src = (const float4*)(arow + khalf);
        __nv_bfloat162* dH = (__nv_bfloat162*)(Ah + lrow * APAD + khalf);
        __nv_bfloat162* dL = (__nv_bfloat162*)(Al + lrow * APAD + khalf);
#pragma unroll
        for (int i = 0; i < 16; i++) {
            float4 f = src[i];
            __nv_bfloat162 h0 = __float22bfloat162_rn(make_float2(f.x, f.y));
            __nv_bfloat162 h1 = __float22bfloat162_rn(make_float2(f.z, f.w));
            float2 hf0 = __bfloat1622float2(h0);
            float2 hf1 = __bfloat1622float2(h1);
            __nv_bfloat162 l0 = __float22bfloat162_rn(
                make_float2(f.x - hf0.x, f.y - hf0.y));
            __nv_bfloat162 l1 = __float22bfloat162_rn(
                make_float2(f.z - hf1.x, f.w - hf1.y));
            dH[2*i]   = h0; dH[2*i+1] = h1;
            dL[2*i]   = l0; dL[2*i+1] = l1;
        }
    }
    __syncthreads();

    // ---- mma mainloop ----
    const int R      = warp * 16;           // warp's row strip within tile
    const int arow_f = R + (lane >> 2);     // fragment row
    const int kfrag  = (lane & 3) * 2;      // fragment k offset
    const int nfrag  = lane >> 2;           // fragment n offset within n8
    const int cfrag  = (lane & 3) * 2;      // fragment col offset

    float acc[16][4];
#pragma unroll
    for (int i = 0; i < 16; i++)
#pragma unroll
        for (int j = 0; j < 4; j++) acc[i][j] = 0.f;

#pragma unroll
    for (int ks = 0; ks < 8; ks++) {
        const int K0 = ks * 16;
        const __nv_bfloat16* pa = Ah + arow_f * APAD + K0 + kfrag;
        const __nv_bfloat16* pl = Al + arow_f * APAD + K0 + kfrag;
        unsigned ah0 = *(const unsigned*)(pa);
        unsigned ah1 = *(const unsigned*)(pa + 8*APAD);
        unsigned ah2 = *(const unsigned*)(pa + 8);
        unsigned ah3 = *(const unsigned*)(pa + 8*APAD + 8);
        unsigned al0 = *(const unsigned*)(pl);
        unsigned al1 = *(const unsigned*)(pl + 8*APAD);
        unsigned al2 = *(const unsigned*)(pl + 8);
        unsigned al3 = *(const unsigned*)(pl + 8*APAD + 8);

#pragma unroll
        for (int nt = 0; nt < 16; nt++) {
            const __nv_bfloat16* pbh = Bh + (nt*8 + nfrag) * APAD + K0 + kfrag;
            const __nv_bfloat16* pbl = Bl + (nt*8 + nfrag) * APAD + K0 + kfrag;
            unsigned bh0 = *(const unsigned*)(pbh);
            unsigned bh1 = *(const unsigned*)(pbh + 8);
            unsigned bl0 = *(const unsigned*)(pbl);
            unsigned bl1 = *(const unsigned*)(pbl + 8);
            mma_bf16(acc[nt][0], acc[nt][1], acc[nt][2], acc[nt][3],
                     ah0, ah1, ah2, ah3, bh0, bh1);
            mma_bf16(acc[nt][0], acc[nt][1], acc[nt][2], acc[nt][3],
                     ah0, ah1, ah2, ah3, bl0, bl1);
            mma_bf16(acc[nt][0], acc[nt][1], acc[nt][2], acc[nt][3],
                     al0, al1, al2, al3, bh0, bh1);
        }
    }

    // ---- epilogue: add bias, store ----
    const int row_g = row0 + R + (lane >> 2);
#pragma unroll
    for (int nt = 0; nt < 16; nt++) {
        const int col = nt*8 + cfrag;
        const float2 bb = *(const float2*)&g_b2[col];
        float2 o0 = make_float2(acc[nt][0] + bb.x, acc[nt][1] + bb.y);
        float2 o1 = make_float2(acc[nt][2] + bb.x, acc[nt][3] + bb.y);
        *(float2*)&C[(size_t)row_g * D_ + col]       = o0;
        *(float2*)&C[(size_t)(row_g + 8) * D_ + col] = o1;
    }
}

// ---------------------------------------------------------------------------
extern "C" void kernel_launch(void* const* d_in, const int* in_sizes, int n_in,
                              void* d_out, int out_size)
{
    const float* v    = (const float*)d_in[0];
    const float* k    = (const float*)d_in[1];
    const float* q    = (const float*)d_in[2];
    const float* mask = (const float*)d_in[3];
    const float* Wq   = (const float*)d_in[4];
    const float* bq   = (const float*)d_in[5];
    const float* Wk   = (const float*)d_in[6];
    const float* bk   = (const float*)d_in[7];
    const float* Wv   = (const float*)d_in[8];
    const float* bv   = (const float*)d_in[9];
    const float* Wo   = (const float*)d_in[10];
    const float* bo   = (const float*)d_in[11];
    float* out = (float*)d_out;

    const int hasAttn = (out_size >= OUT_ELEMS + ATTN_ELEMS) ? 1 : 0;
    float* attnOut = hasAttn ? (out + OUT_ELEMS) : nullptr;

    cudaFuncSetAttribute(gemm_mma,
                         cudaFuncAttributeMaxDynamicSharedMemorySize,
                         SMEM_BYTES);

    // 1. Candidate sets per mask row
    mask_cand<<<SP_ / 8, 256>>>(mask);

    // 2. W2 hi/lo + b2 prep + rare-row attention
    fused_prep<<<65 + SP_, 256>>>(Wv, Wo, bv, bo, q, k, v, mask,
                                  Wq, bq, Wk, bk);

    // 3. Attention output (store-bound, near HBM write floor)
    if (hasAttn) attn_write<<<NROWS / 8, 256>>>(attnOut);

    // 4. out = gather(v) @ W2 + b2  (tensor cores, bf16x3)
    gemm_mma<<<GEMM_BLOCKS, 256, SMEM_BYTES>>>(v, out);
}